// round 1
// baseline (speedup 1.0000x reference)
#include <cuda_runtime.h>
#include <cstdint>

// Problem constants
#define BATCH 1024
#define NN    128     // n_node
#define DIN   256
#define HID   256
#define DOUT  256
#define KD    512     // 4*N
#define MROWS (BATCH*NN)          // 131072

#define OUT_ELEMS ((long)MROWS*DOUT)        // 33,554,432
#define ATT_ELEMS ((long)BATCH*NN*NN)       // 16,777,216
#define TOT_ELEMS (OUT_ELEMS + ATT_ELEMS)   // 50,331,648

// ---------------- scratch (device globals; no allocation allowed) -------------
__device__ float g_v  [(long)MROWS*HID];   // 134 MB
__device__ float g_q  [(long)MROWS*KD];    // 268 MB
__device__ float g_k  [(long)MROWS*KD];    // 268 MB
__device__ float g_ctx[(long)MROWS*HID];   // 134 MB
__device__ float g_att_dummy[ATT_ELEMS];   // used only if harness wants 'out' alone

// =====================================================================
// Dense GEMM + bias + relu:  C[M,Ncols] = relu(A[M,K] @ W[K,Ncols] + b)
// 128x128 block tile, 8x8 per thread, K-tile 16, 256 threads.
// =====================================================================
#define BM 128
#define BN 128
#define BK 16

__global__ void __launch_bounds__(256, 2) gemm_relu_kernel(
    const float* __restrict__ A, const float* __restrict__ W,
    const float* __restrict__ bias, float* __restrict__ C,
    int K, int Ncols)
{
    __shared__ float As[BK][BM + 4];
    __shared__ float Bs[BK][BN + 4];

    const int tid = threadIdx.x;
    const int tx = tid & 15;         // 0..15 -> col group
    const int ty = tid >> 4;         // 0..15 -> row group
    const long blockRow = (long)blockIdx.y * BM;
    const int  blockCol = blockIdx.x * BN;

    const float* Ablk = A + blockRow * K;
    const float* Wblk = W + blockCol;

    float acc[8][8];
    #pragma unroll
    for (int i = 0; i < 8; i++)
        #pragma unroll
        for (int j = 0; j < 8; j++) acc[i][j] = 0.f;

    for (int kk = 0; kk < K; kk += BK) {
        // load A tile 128x16 (store transposed: As[k][m])
        #pragma unroll
        for (int l = 0; l < 8; l++) {
            int idx = tid + l * 256;      // 0..2047
            int r = idx >> 4;             // /16  -> m
            int c = idx & 15;             //      -> k
            As[c][r] = Ablk[(long)r * K + kk + c];
        }
        // load W tile 16x128 (Bs[k][n]) — coalesced 128-wide rows
        #pragma unroll
        for (int l = 0; l < 8; l++) {
            int idx = tid + l * 256;
            int r = idx >> 7;             // /128 -> k
            int c = idx & 127;            //      -> n
            Bs[r][c] = Wblk[(long)(kk + r) * Ncols + c];
        }
        __syncthreads();

        #pragma unroll
        for (int t = 0; t < BK; t++) {
            float a[8], bb[8];
            #pragma unroll
            for (int i = 0; i < 8; i++) a[i]  = As[t][ty * 8 + i];
            #pragma unroll
            for (int j = 0; j < 8; j++) bb[j] = Bs[t][tx * 8 + j];
            #pragma unroll
            for (int i = 0; i < 8; i++)
                #pragma unroll
                for (int j = 0; j < 8; j++)
                    acc[i][j] += a[i] * bb[j];
        }
        __syncthreads();
    }

    // epilogue: bias + relu
    #pragma unroll
    for (int i = 0; i < 8; i++) {
        long row = blockRow + ty * 8 + i;
        float* crow = C + row * Ncols + blockCol + tx * 8;
        #pragma unroll
        for (int j = 0; j < 8; j++) {
            float vv = acc[i][j] + bias[blockCol + tx * 8 + j];
            crow[j] = fmaxf(vv, 0.f);
        }
    }
}

// =====================================================================
// Fused attention per batch: scores = q@k^T (K=512), masked softmax,
// ctx = att@v.  One CTA per batch, 256 threads, 192KB dyn smem.
//   smem layout:
//     [0 .. 16384)            s_sc  : scores / probs  128x128
//     [16384 .. 16384+8448)   s_qt  : q tile transposed [64][132]   (phase1)
//     [+8448  .. +16896)      s_kt  : k tile transposed [64][132]   (phase1)
//     [16384 .. 16384+32768)  s_vt  : v  [128][256]                 (phase3)
// =====================================================================
#define ATT_SMEM_FLOATS (16384 + 32768)
#define ATT_SMEM_BYTES  (ATT_SMEM_FLOATS * 4)

__global__ void __launch_bounds__(256, 1) attention_kernel(
    const float* __restrict__ q, const float* __restrict__ k,
    const float* __restrict__ v, const float* __restrict__ mask,
    float* __restrict__ att, float* __restrict__ ctx)
{
    extern __shared__ float sm[];
    float* s_sc = sm;                 // 128*128
    float* s_qt = sm + 16384;         // 64*132
    float* s_kt = s_qt + 64 * 132;    // 64*132
    float* s_vt = sm + 16384;         // 128*256 (reuses q/k region)

    const int b   = blockIdx.x;
    const int tid = threadIdx.x;
    const int tx = tid & 15;
    const int ty = tid >> 4;

    const float* qb = q + (long)b * NN * KD;
    const float* kb = k + (long)b * NN * KD;

    // ---------- phase 1: scores = q @ k^T ----------
    float acc[8][8];
    #pragma unroll
    for (int i = 0; i < 8; i++)
        #pragma unroll
        for (int j = 0; j < 8; j++) acc[i][j] = 0.f;

    for (int kk = 0; kk < KD; kk += 64) {
        #pragma unroll 4
        for (int l = 0; l < 32; l++) {
            int idx = tid + l * 256;   // 0..8191
            int n = idx >> 6;          // /64 -> row
            int c = idx & 63;          //     -> k within tile
            s_qt[c * 132 + n] = qb[(long)n * KD + kk + c];
            s_kt[c * 132 + n] = kb[(long)n * KD + kk + c];
        }
        __syncthreads();
        #pragma unroll
        for (int t = 0; t < 64; t++) {
            float a[8], bb[8];
            #pragma unroll
            for (int i = 0; i < 8; i++) a[i]  = s_qt[t * 132 + ty * 8 + i];
            #pragma unroll
            for (int j = 0; j < 8; j++) bb[j] = s_kt[t * 132 + tx * 8 + j];
            #pragma unroll
            for (int i = 0; i < 8; i++)
                #pragma unroll
                for (int j = 0; j < 8; j++)
                    acc[i][j] += a[i] * bb[j];
        }
        __syncthreads();
    }
    #pragma unroll
    for (int i = 0; i < 8; i++)
        #pragma unroll
        for (int j = 0; j < 8; j++)
            s_sc[(ty * 8 + i) * 128 + tx * 8 + j] = acc[i][j];
    __syncthreads();

    // ---------- phase 2: masked softmax (rows) ----------
    {
        const int warp = tid >> 5;
        const int lane = tid & 31;
        const float* mb = mask + (long)b * NN * NN;
        float* attb = att + (long)b * NN * NN;
        for (int r = 0; r < 16; r++) {
            int row = warp * 16 + r;
            float vals[4];
            float mx = -1e30f;
            #pragma unroll
            for (int c = 0; c < 4; c++) {
                int col = lane + c * 32;
                float m  = mb[row * 128 + col];
                float sc = s_sc[row * 128 + col];
                float vv = sc * m - 1000.0f * (1.0f - m);
                vals[c] = vv;
                mx = fmaxf(mx, vv);
            }
            #pragma unroll
            for (int off = 16; off; off >>= 1)
                mx = fmaxf(mx, __shfl_xor_sync(0xffffffffu, mx, off));
            float sum = 0.f;
            #pragma unroll
            for (int c = 0; c < 4; c++) {
                vals[c] = __expf(vals[c] - mx);
                sum += vals[c];
            }
            #pragma unroll
            for (int off = 16; off; off >>= 1)
                sum += __shfl_xor_sync(0xffffffffu, sum, off);
            float inv = 1.0f / sum;
            #pragma unroll
            for (int c = 0; c < 4; c++) {
                int col = lane + c * 32;
                float p = vals[c] * inv;
                s_sc[row * 128 + col] = p;
                attb[row * 128 + col] = p;
            }
        }
    }
    __syncthreads();

    // ---------- phase 3: ctx = att @ v ----------
    {
        const float* vb = v + (long)b * NN * HID;
        #pragma unroll 8
        for (int l = 0; l < 128; l++)
            s_vt[tid + l * 256] = vb[tid + l * 256];
        __syncthreads();

        float* ctxb = ctx + (long)b * NN * HID;
        for (int nb2 = 0; nb2 < 2; nb2++) {
            float acc2[8][8];
            #pragma unroll
            for (int i = 0; i < 8; i++)
                #pragma unroll
                for (int j = 0; j < 8; j++) acc2[i][j] = 0.f;
            #pragma unroll 4
            for (int t = 0; t < 128; t++) {
                float a[8], bb[8];
                #pragma unroll
                for (int i = 0; i < 8; i++) a[i]  = s_sc[(ty * 8 + i) * 128 + t];
                #pragma unroll
                for (int j = 0; j < 8; j++) bb[j] = s_vt[t * 256 + nb2 * 128 + tx * 8 + j];
                #pragma unroll
                for (int i = 0; i < 8; i++)
                    #pragma unroll
                    for (int j = 0; j < 8; j++)
                        acc2[i][j] += a[i] * bb[j];
            }
            #pragma unroll
            for (int i = 0; i < 8; i++) {
                float* crow = ctxb + (ty * 8 + i) * HID + nb2 * 128 + tx * 8;
                #pragma unroll
                for (int j = 0; j < 8; j++) crow[j] = acc2[i][j];
            }
        }
    }
}

// =====================================================================
extern "C" void kernel_launch(void* const* d_in, const int* in_sizes, int n_in,
                              void* d_out, int out_size)
{
    const float* x    = (const float*)d_in[0];
    const float* mask = (const float*)d_in[1];
    const float* Wv   = (const float*)d_in[2];
    const float* bv   = (const float*)d_in[3];
    const float* Wq   = (const float*)d_in[4];
    const float* bq   = (const float*)d_in[5];
    const float* Wk   = (const float*)d_in[6];
    const float* bk   = (const float*)d_in[7];
    const float* Wo   = (const float*)d_in[8];
    const float* bo   = (const float*)d_in[9];

    float* out = (float*)d_out;

    float *pv, *pq, *pk, *pctx, *pattd;
    cudaGetSymbolAddress((void**)&pv,   g_v);
    cudaGetSymbolAddress((void**)&pq,   g_q);
    cudaGetSymbolAddress((void**)&pk,   g_k);
    cudaGetSymbolAddress((void**)&pctx, g_ctx);
    cudaGetSymbolAddress((void**)&pattd, g_att_dummy);

    // output tuple (out, att): out first, att second if the buffer holds both
    float* patt = ((long)out_size >= TOT_ELEMS) ? (out + OUT_ELEMS) : pattd;

    cudaFuncSetAttribute(attention_kernel,
                         cudaFuncAttributeMaxDynamicSharedMemorySize,
                         ATT_SMEM_BYTES);

    dim3 thr(256);
    // v = relu(x @ Wv + bv)    [131072, 256] x [256,256]
    gemm_relu_kernel<<<dim3(HID / BN, MROWS / BM), thr>>>(x, Wv, bv, pv, DIN, HID);
    // q = relu(x @ Wq + bq)    [131072, 256] x [256,512]
    gemm_relu_kernel<<<dim3(KD  / BN, MROWS / BM), thr>>>(x, Wq, bq, pq, DIN, KD);
    // k = relu(x @ Wk + bk)
    gemm_relu_kernel<<<dim3(KD  / BN, MROWS / BM), thr>>>(x, Wk, bk, pk, DIN, KD);

    // fused scores -> masked softmax -> ctx (one CTA per batch)
    attention_kernel<<<BATCH, thr, ATT_SMEM_BYTES>>>(pq, pk, pv, mask, patt, pctx);

    // out = relu(ctx @ Wo + bo)
    gemm_relu_kernel<<<dim3(DOUT / BN, MROWS / BM), thr>>>(pctx, Wo, bo, out, HID, DOUT);
}

// round 3
// speedup vs baseline: 1.9666x; 1.9666x over previous
#include <cuda_runtime.h>
#include <cuda_bf16.h>
#include <cstdint>

// ---------------- problem constants ----------------
#define BATCH 1024
#define NN    128
#define DIN   256
#define HID   256
#define DOUT  256
#define KD    512
#define MROWS (BATCH*NN)                    // 131072
#define GK    256                           // K of every dense GEMM

#define OUT_ELEMS ((long)MROWS*DOUT)
#define ATT_ELEMS ((long)BATCH*NN*NN)
#define TOT_ELEMS (OUT_ELEMS + ATT_ELEMS)

// ---------------- scratch (device globals) ----------------
__device__ __align__(16) float g_v [(long)MROWS*HID];
__device__ __align__(16) float g_q [(long)MROWS*KD];
__device__ __align__(16) float g_k [(long)MROWS*KD];
__device__ __align__(16) float g_att_dummy[ATT_ELEMS];

__device__ __align__(16) __nv_bfloat16 g_xhi[(long)MROWS*GK];
__device__ __align__(16) __nv_bfloat16 g_xlo[(long)MROWS*GK];
__device__ __align__(16) __nv_bfloat16 g_chi[(long)MROWS*HID];
__device__ __align__(16) __nv_bfloat16 g_clo[(long)MROWS*HID];

// weights: transposed [N,K] bf16 hi/lo
__device__ __align__(16) __nv_bfloat16 g_wvhi[GK*HID], g_wvlo[GK*HID];
__device__ __align__(16) __nv_bfloat16 g_wqhi[GK*KD],  g_wqlo[GK*KD];
__device__ __align__(16) __nv_bfloat16 g_wkhi[GK*KD],  g_wklo[GK*KD];
__device__ __align__(16) __nv_bfloat16 g_wohi[HID*DOUT], g_wolo[HID*DOUT];

// ---------------- helpers ----------------
__device__ __forceinline__ uint32_t smem_u32(const void* p) {
    uint32_t a;
    asm("{ .reg .u64 t; cvta.to.shared.u64 t, %1; cvt.u32.u64 %0, t; }" : "=r"(a) : "l"(p));
    return a;
}
__device__ __forceinline__ void split_bf16(float a, __nv_bfloat16& h, __nv_bfloat16& l) {
    h = __float2bfloat16_rn(a);
    l = __float2bfloat16_rn(a - __bfloat162float(h));
}

#define LDSM4(r0, r1, r2, r3, addr) \
    asm volatile("ldmatrix.sync.aligned.m8n8.x4.shared.b16 {%0,%1,%2,%3}, [%4];" \
                 : "=r"(r0), "=r"(r1), "=r"(r2), "=r"(r3) : "r"(addr))

#define MMA16816(d, a0, a1, a2, a3, b0, b1) \
    asm volatile("mma.sync.aligned.m16n8k16.row.col.f32.bf16.bf16.f32 " \
                 "{%0,%1,%2,%3},{%4,%5,%6,%7},{%8,%9},{%0,%1,%2,%3};" \
                 : "+f"((d)[0]), "+f"((d)[1]), "+f"((d)[2]), "+f"((d)[3]) \
                 : "r"(a0), "r"(a1), "r"(a2), "r"(a3), "r"(b0), "r"(b1))

// ---------------- prep kernels ----------------
__global__ void split_x_kernel(const float4* __restrict__ x,
                               uint2* __restrict__ hi, uint2* __restrict__ lo, long n4) {
    long i = (long)blockIdx.x * blockDim.x + threadIdx.x;
    if (i >= n4) return;
    float4 a = x[i];
    __nv_bfloat16 h0, l0, h1, l1, h2, l2, h3, l3;
    split_bf16(a.x, h0, l0); split_bf16(a.y, h1, l1);
    split_bf16(a.z, h2, l2); split_bf16(a.w, h3, l3);
    __nv_bfloat162 hA = __halves2bfloat162(h0, h1), hB = __halves2bfloat162(h2, h3);
    __nv_bfloat162 lA = __halves2bfloat162(l0, l1), lB = __halves2bfloat162(l2, l3);
    hi[i] = make_uint2(*(uint32_t*)&hA, *(uint32_t*)&hB);
    lo[i] = make_uint2(*(uint32_t*)&lA, *(uint32_t*)&lB);
}

__global__ void prep_weight(const float* __restrict__ W, __nv_bfloat16* __restrict__ hi,
                            __nv_bfloat16* __restrict__ lo, int K, int N) {
    int idx = blockIdx.x * 256 + threadIdx.x;
    if (idx >= K * N) return;
    int k = idx / N, n = idx % N;
    __nv_bfloat16 h, l;
    split_bf16(W[idx], h, l);
    hi[(long)n * K + k] = h;
    lo[(long)n * K + k] = l;
}

// =====================================================================
// bf16x3 mma.sync GEMM: C[M,Ncols] = relu(A @ W + b),  A=[M,256] (hi/lo bf16),
// W given transposed [Ncols,256] hi/lo.  CTA tile 128x128, K-tile 64,
// 8 warps (4m x 2n), warp tile 32x64, HMMA m16n8k16.
// =====================================================================
#define ROWB 144                    // smem bytes per 64-bf16 row (padded)
#define TILE_B (128 * ROWB)         // 18432
#define GEMM_SMEM (4 * TILE_B)      // 73728

__global__ void __launch_bounds__(256, 2) mma_gemm(
    const __nv_bfloat16* __restrict__ Ahi, const __nv_bfloat16* __restrict__ Alo,
    const __nv_bfloat16* __restrict__ Bhi, const __nv_bfloat16* __restrict__ Blo,
    const float* __restrict__ bias, float* __restrict__ C, int Ncols)
{
    extern __shared__ char smc[];
    const uint32_t sAh = smem_u32(smc);
    const uint32_t sAl = sAh + TILE_B;
    const uint32_t sBh = sAh + 2 * TILE_B;
    const uint32_t sBl = sAh + 3 * TILE_B;

    const int tid  = threadIdx.x;
    const int wid  = tid >> 5;
    const int lane = tid & 31;
    const int wm   = wid >> 1;          // 0..3
    const int wn   = wid & 1;           // 0..1

    const long mBase = (long)blockIdx.y * 128;
    const int  nBase = blockIdx.x * 128;

    const __nv_bfloat16* Ah = Ahi + mBase * GK;
    const __nv_bfloat16* Al = Alo + mBase * GK;
    const __nv_bfloat16* Bh = Bhi + (long)nBase * GK;
    const __nv_bfloat16* Bl = Blo + (long)nBase * GK;

    float acc[2][8][4];
    #pragma unroll
    for (int a = 0; a < 2; a++)
        #pragma unroll
        for (int b = 0; b < 8; b++)
            #pragma unroll
            for (int c = 0; c < 4; c++) acc[a][b][c] = 0.f;

    const int lrow = tid >> 3;          // 0..31
    const int lq   = tid & 7;           // 0..7 (16B chunk in row)

    // per-lane ldmatrix base offsets
    const uint32_t aOff = (uint32_t)(wm * 32 + (lane & 15)) * ROWB + (lane >> 4) * 16;
    const uint32_t bOff = (uint32_t)(wn * 64 + (lane & 15)) * ROWB + (lane >> 4) * 16;

    for (int kt = 0; kt < 4; kt++) {
        __syncthreads();
        // ---- load K-tile (64 cols) of A hi/lo and B hi/lo ----
        #pragma unroll
        for (int it = 0; it < 4; it++) {
            int r = lrow + it * 32;
            long gsrc = (long)r * GK + kt * 64 + lq * 8;
            uint32_t sdst = (uint32_t)r * ROWB + lq * 16;
            *(uint4*)(smc + (sAh - smem_u32(smc)) + sdst) = *(const uint4*)(Ah + gsrc);
            *(uint4*)(smc + (sAl - smem_u32(smc)) + sdst) = *(const uint4*)(Al + gsrc);
            *(uint4*)(smc + (sBh - smem_u32(smc)) + sdst) = *(const uint4*)(Bh + gsrc);
            *(uint4*)(smc + (sBl - smem_u32(smc)) + sdst) = *(const uint4*)(Bl + gsrc);
        }
        __syncthreads();

        // ---- compute 4 k-steps of 16 ----
        #pragma unroll
        for (int ks = 0; ks < 4; ks++) {
            const uint32_t kByte = ks * 32;   // 16 bf16 = 32B
            uint32_t Bf[16], Af[8], Af2[8];

            #pragma unroll
            for (int c = 0; c < 4; c++) {
                uint32_t ad = sBh + bOff + (uint32_t)c * (16 * ROWB) + kByte;
                LDSM4(Bf[c*4+0], Bf[c*4+1], Bf[c*4+2], Bf[c*4+3], ad);
            }
            #pragma unroll
            for (int mt = 0; mt < 2; mt++) {
                uint32_t ad = sAh + aOff + (uint32_t)mt * (16 * ROWB) + kByte;
                LDSM4(Af[mt*4+0], Af[mt*4+1], Af[mt*4+2], Af[mt*4+3], ad);
            }
            #pragma unroll
            for (int mt = 0; mt < 2; mt++) {
                uint32_t ad = sAl + aOff + (uint32_t)mt * (16 * ROWB) + kByte;
                LDSM4(Af2[mt*4+0], Af2[mt*4+1], Af2[mt*4+2], Af2[mt*4+3], ad);
            }
            // hi*hi and lo*hi
            #pragma unroll
            for (int mt = 0; mt < 2; mt++)
                #pragma unroll
                for (int c = 0; c < 4; c++) {
                    MMA16816(acc[mt][c*2+0], Af[mt*4+0], Af[mt*4+1], Af[mt*4+2], Af[mt*4+3],
                             Bf[c*4+0], Bf[c*4+2]);
                    MMA16816(acc[mt][c*2+1], Af[mt*4+0], Af[mt*4+1], Af[mt*4+2], Af[mt*4+3],
                             Bf[c*4+1], Bf[c*4+3]);
                    MMA16816(acc[mt][c*2+0], Af2[mt*4+0], Af2[mt*4+1], Af2[mt*4+2], Af2[mt*4+3],
                             Bf[c*4+0], Bf[c*4+2]);
                    MMA16816(acc[mt][c*2+1], Af2[mt*4+0], Af2[mt*4+1], Af2[mt*4+2], Af2[mt*4+3],
                             Bf[c*4+1], Bf[c*4+3]);
                }
            // hi*lo (reload B from lo tile into same regs)
            #pragma unroll
            for (int c = 0; c < 4; c++) {
                uint32_t ad = sBl + bOff + (uint32_t)c * (16 * ROWB) + kByte;
                LDSM4(Bf[c*4+0], Bf[c*4+1], Bf[c*4+2], Bf[c*4+3], ad);
            }
            #pragma unroll
            for (int mt = 0; mt < 2; mt++)
                #pragma unroll
                for (int c = 0; c < 4; c++) {
                    MMA16816(acc[mt][c*2+0], Af[mt*4+0], Af[mt*4+1], Af[mt*4+2], Af[mt*4+3],
                             Bf[c*4+0], Bf[c*4+2]);
                    MMA16816(acc[mt][c*2+1], Af[mt*4+0], Af[mt*4+1], Af[mt*4+2], Af[mt*4+3],
                             Bf[c*4+1], Bf[c*4+3]);
                }
        }
    }

    // ---- epilogue: bias + relu, direct reg->gmem ----
    const int group = lane >> 2;
    const int tig   = lane & 3;
    #pragma unroll
    for (int mt = 0; mt < 2; mt++) {
        long r0 = mBase + wm * 32 + mt * 16 + group;
        long r1 = r0 + 8;
        #pragma unroll
        for (int nt = 0; nt < 8; nt++) {
            int col = nBase + wn * 64 + (nt >> 1) * 16 + (nt & 1) * 8 + tig * 2;
            float b0 = bias[col], b1 = bias[col + 1];
            float* p0 = C + r0 * Ncols + col;
            float* p1 = C + r1 * Ncols + col;
            float2 v0 = make_float2(fmaxf(acc[mt][nt][0] + b0, 0.f),
                                    fmaxf(acc[mt][nt][1] + b1, 0.f));
            float2 v1 = make_float2(fmaxf(acc[mt][nt][2] + b0, 0.f),
                                    fmaxf(acc[mt][nt][3] + b1, 0.f));
            *(float2*)p0 = v0;
            *(float2*)p1 = v1;
        }
    }
}

// =====================================================================
// Fused attention (FFMA; ctx written as bf16 hi/lo split)
// =====================================================================
#define ATT_SMEM_FLOATS (16384 + 32768)
#define ATT_SMEM_BYTES  (ATT_SMEM_FLOATS * 4)

__global__ void __launch_bounds__(256, 1) attention_kernel(
    const float* __restrict__ q, const float* __restrict__ k,
    const float* __restrict__ v, const float* __restrict__ mask,
    float* __restrict__ att,
    __nv_bfloat16* __restrict__ ctxhi, __nv_bfloat16* __restrict__ ctxlo)
{
    extern __shared__ float sm[];
    float* s_sc = sm;
    float* s_qt = sm + 16384;
    float* s_kt = s_qt + 64 * 132;
    float* s_vt = sm + 16384;

    const int b   = blockIdx.x;
    const int tid = threadIdx.x;
    const int tx = tid & 15;
    const int ty = tid >> 4;

    const float* qb = q + (long)b * NN * KD;
    const float* kb = k + (long)b * NN * KD;

    float acc[8][8];
    #pragma unroll
    for (int i = 0; i < 8; i++)
        #pragma unroll
        for (int j = 0; j < 8; j++) acc[i][j] = 0.f;

    for (int kk = 0; kk < KD; kk += 64) {
        #pragma unroll 4
        for (int l = 0; l < 32; l++) {
            int idx = tid + l * 256;
            int n = idx >> 6;
            int c = idx & 63;
            s_qt[c * 132 + n] = qb[(long)n * KD + kk + c];
            s_kt[c * 132 + n] = kb[(long)n * KD + kk + c];
        }
        __syncthreads();
        #pragma unroll
        for (int t = 0; t < 64; t++) {
            float a[8], bb[8];
            #pragma unroll
            for (int i = 0; i < 8; i++) a[i]  = s_qt[t * 132 + ty * 8 + i];
            #pragma unroll
            for (int j = 0; j < 8; j++) bb[j] = s_kt[t * 132 + tx * 8 + j];
            #pragma unroll
            for (int i = 0; i < 8; i++)
                #pragma unroll
                for (int j = 0; j < 8; j++)
                    acc[i][j] += a[i] * bb[j];
        }
        __syncthreads();
    }
    #pragma unroll
    for (int i = 0; i < 8; i++)
        #pragma unroll
        for (int j = 0; j < 8; j++)
            s_sc[(ty * 8 + i) * 128 + tx * 8 + j] = acc[i][j];
    __syncthreads();

    {
        const int warp = tid >> 5;
        const int lane = tid & 31;
        const float* mb = mask + (long)b * NN * NN;
        float* attb = att + (long)b * NN * NN;
        for (int r = 0; r < 16; r++) {
            int row = warp * 16 + r;
            float vals[4];
            float mx = -1e30f;
            #pragma unroll
            for (int c = 0; c < 4; c++) {
                int col = lane + c * 32;
                float m  = mb[row * 128 + col];
                float sc = s_sc[row * 128 + col];
                float vv = sc * m - 1000.0f * (1.0f - m);
                vals[c] = vv;
                mx = fmaxf(mx, vv);
            }
            #pragma unroll
            for (int off = 16; off; off >>= 1)
                mx = fmaxf(mx, __shfl_xor_sync(0xffffffffu, mx, off));
            float sum = 0.f;
            #pragma unroll
            for (int c = 0; c < 4; c++) {
                vals[c] = __expf(vals[c] - mx);
                sum += vals[c];
            }
            #pragma unroll
            for (int off = 16; off; off >>= 1)
                sum += __shfl_xor_sync(0xffffffffu, sum, off);
            float inv = 1.0f / sum;
            #pragma unroll
            for (int c = 0; c < 4; c++) {
                int col = lane + c * 32;
                float p = vals[c] * inv;
                s_sc[row * 128 + col] = p;
                attb[row * 128 + col] = p;
            }
        }
    }
    __syncthreads();

    {
        const float* vb = v + (long)b * NN * HID;
        #pragma unroll 8
        for (int l = 0; l < 128; l++)
            s_vt[tid + l * 256] = vb[tid + l * 256];
        __syncthreads();

        __nv_bfloat16* chb = ctxhi + (long)b * NN * HID;
        __nv_bfloat16* clb = ctxlo + (long)b * NN * HID;
        for (int nb2 = 0; nb2 < 2; nb2++) {
            float acc2[8][8];
            #pragma unroll
            for (int i = 0; i < 8; i++)
                #pragma unroll
                for (int j = 0; j < 8; j++) acc2[i][j] = 0.f;
            #pragma unroll 4
            for (int t = 0; t < 128; t++) {
                float a[8], bb[8];
                #pragma unroll
                for (int i = 0; i < 8; i++) a[i]  = s_sc[(ty * 8 + i) * 128 + t];
                #pragma unroll
                for (int j = 0; j < 8; j++) bb[j] = s_vt[t * 256 + nb2 * 128 + tx * 8 + j];
                #pragma unroll
                for (int i = 0; i < 8; i++)
                    #pragma unroll
                    for (int j = 0; j < 8; j++)
                        acc2[i][j] += a[i] * bb[j];
            }
            #pragma unroll
            for (int i = 0; i < 8; i++) {
                long base = ((long)(ty * 8 + i)) * HID + nb2 * 128 + tx * 8;
                #pragma unroll
                for (int j = 0; j < 8; j++) {
                    float vv = acc2[i][j];
                    __nv_bfloat16 h, l;
                    split_bf16(vv, h, l);
                    chb[base + j] = h;
                    clb[base + j] = l;
                }
            }
        }
    }
}

// =====================================================================
extern "C" void kernel_launch(void* const* d_in, const int* in_sizes, int n_in,
                              void* d_out, int out_size)
{
    const float* x    = (const float*)d_in[0];
    const float* mask = (const float*)d_in[1];
    const float* Wv   = (const float*)d_in[2];
    const float* bv   = (const float*)d_in[3];
    const float* Wq   = (const float*)d_in[4];
    const float* bq   = (const float*)d_in[5];
    const float* Wk   = (const float*)d_in[6];
    const float* bk   = (const float*)d_in[7];
    const float* Wo   = (const float*)d_in[8];
    const float* bo   = (const float*)d_in[9];

    float* out = (float*)d_out;

    float *pv, *pq, *pk, *pattd;
    cudaGetSymbolAddress((void**)&pv,    g_v);
    cudaGetSymbolAddress((void**)&pq,    g_q);
    cudaGetSymbolAddress((void**)&pk,    g_k);
    cudaGetSymbolAddress((void**)&pattd, g_att_dummy);

    __nv_bfloat16 *xhi, *xlo, *chi, *clo;
    cudaGetSymbolAddress((void**)&xhi, g_xhi);
    cudaGetSymbolAddress((void**)&xlo, g_xlo);
    cudaGetSymbolAddress((void**)&chi, g_chi);
    cudaGetSymbolAddress((void**)&clo, g_clo);

    __nv_bfloat16 *wvhi, *wvlo, *wqhi, *wqlo, *wkhi, *wklo, *wohi, *wolo;
    cudaGetSymbolAddress((void**)&wvhi, g_wvhi);
    cudaGetSymbolAddress((void**)&wvlo, g_wvlo);
    cudaGetSymbolAddress((void**)&wqhi, g_wqhi);
    cudaGetSymbolAddress((void**)&wqlo, g_wqlo);
    cudaGetSymbolAddress((void**)&wkhi, g_wkhi);
    cudaGetSymbolAddress((void**)&wklo, g_wklo);
    cudaGetSymbolAddress((void**)&wohi, g_wohi);
    cudaGetSymbolAddress((void**)&wolo, g_wolo);

    float* patt = ((long)out_size >= TOT_ELEMS) ? (out + OUT_ELEMS) : pattd;

    cudaFuncSetAttribute(attention_kernel,
                         cudaFuncAttributeMaxDynamicSharedMemorySize, ATT_SMEM_BYTES);
    cudaFuncSetAttribute(mma_gemm,
                         cudaFuncAttributeMaxDynamicSharedMemorySize, GEMM_SMEM);

    // prep: split x, split+transpose weights
    {
        long n4 = (long)MROWS * GK / 4;
        split_x_kernel<<<(unsigned)((n4 + 255) / 256), 256>>>(
            (const float4*)x, (uint2*)xhi, (uint2*)xlo, n4);
    }
    prep_weight<<<(GK*HID  + 255)/256, 256>>>(Wv, wvhi, wvlo, GK, HID);
    prep_weight<<<(GK*KD   + 255)/256, 256>>>(Wq, wqhi, wqlo, GK, KD);
    prep_weight<<<(GK*KD   + 255)/256, 256>>>(Wk, wkhi, wklo, GK, KD);
    prep_weight<<<(HID*DOUT+ 255)/256, 256>>>(Wo, wohi, wolo, HID, DOUT);

    const int mTiles = MROWS / 128;   // 1024
    mma_gemm<<<dim3(HID/128, mTiles), 256, GEMM_SMEM>>>(xhi, xlo, wvhi, wvlo, bv, pv, HID);
    mma_gemm<<<dim3(KD/128,  mTiles), 256, GEMM_SMEM>>>(xhi, xlo, wqhi, wqlo, bq, pq, KD);
    mma_gemm<<<dim3(KD/128,  mTiles), 256, GEMM_SMEM>>>(xhi, xlo, wkhi, wklo, bk, pk, KD);

    attention_kernel<<<BATCH, 256, ATT_SMEM_BYTES>>>(pq, pk, pv, mask, patt, chi, clo);

    mma_gemm<<<dim3(DOUT/128, mTiles), 256, GEMM_SMEM>>>(chi, clo, wohi, wolo, bo, out, DOUT);
}

// round 4
// speedup vs baseline: 2.4993x; 1.2709x over previous
#include <cuda_runtime.h>
#include <cuda_bf16.h>
#include <cstdint>

// ---------------- problem constants ----------------
#define BATCH 1024
#define NN    128
#define DIN   256
#define HID   256
#define DOUT  256
#define KD    512
#define MROWS (BATCH*NN)
#define GK    256

#define OUT_ELEMS ((long)MROWS*DOUT)
#define ATT_ELEMS ((long)BATCH*NN*NN)
#define TOT_ELEMS (OUT_ELEMS + ATT_ELEMS)

// ---------------- scratch ----------------
__device__ __align__(16) float g_att_dummy[ATT_ELEMS];

__device__ __align__(16) __nv_bfloat16 g_xhi[(long)MROWS*GK];
__device__ __align__(16) __nv_bfloat16 g_xlo[(long)MROWS*GK];
__device__ __align__(16) __nv_bfloat16 g_qhi[(long)MROWS*KD];
__device__ __align__(16) __nv_bfloat16 g_qlo[(long)MROWS*KD];
__device__ __align__(16) __nv_bfloat16 g_khi[(long)MROWS*KD];
__device__ __align__(16) __nv_bfloat16 g_klo[(long)MROWS*KD];
__device__ __align__(16) __nv_bfloat16 g_vhi[(long)MROWS*HID];
__device__ __align__(16) __nv_bfloat16 g_vlo[(long)MROWS*HID];
__device__ __align__(16) __nv_bfloat16 g_chi[(long)MROWS*HID];
__device__ __align__(16) __nv_bfloat16 g_clo[(long)MROWS*HID];

__device__ __align__(16) __nv_bfloat16 g_wvhi[GK*HID], g_wvlo[GK*HID];
__device__ __align__(16) __nv_bfloat16 g_wqhi[GK*KD],  g_wqlo[GK*KD];
__device__ __align__(16) __nv_bfloat16 g_wkhi[GK*KD],  g_wklo[GK*KD];
__device__ __align__(16) __nv_bfloat16 g_wohi[HID*DOUT], g_wolo[HID*DOUT];

// ---------------- helpers ----------------
__device__ __forceinline__ uint32_t smem_u32(const void* p) {
    uint32_t a;
    asm("{ .reg .u64 t; cvta.to.shared.u64 t, %1; cvt.u32.u64 %0, t; }" : "=r"(a) : "l"(p));
    return a;
}
__device__ __forceinline__ void split_bf16(float a, __nv_bfloat16& h, __nv_bfloat16& l) {
    h = __float2bfloat16_rn(a);
    l = __float2bfloat16_rn(a - __bfloat162float(h));
}

#define LDSM4(r0, r1, r2, r3, addr) \
    asm volatile("ldmatrix.sync.aligned.m8n8.x4.shared.b16 {%0,%1,%2,%3}, [%4];" \
                 : "=r"(r0), "=r"(r1), "=r"(r2), "=r"(r3) : "r"(addr))

#define MMA16816(d, a0, a1, a2, a3, b0, b1) \
    asm volatile("mma.sync.aligned.m16n8k16.row.col.f32.bf16.bf16.f32 " \
                 "{%0,%1,%2,%3},{%4,%5,%6,%7},{%8,%9},{%0,%1,%2,%3};" \
                 : "+f"((d)[0]), "+f"((d)[1]), "+f"((d)[2]), "+f"((d)[3]) \
                 : "r"(a0), "r"(a1), "r"(a2), "r"(a3), "r"(b0), "r"(b1))

// ---------------- prep kernels ----------------
__global__ void split_x_kernel(const float4* __restrict__ x,
                               uint2* __restrict__ hi, uint2* __restrict__ lo, long n4) {
    long i = (long)blockIdx.x * blockDim.x + threadIdx.x;
    if (i >= n4) return;
    float4 a = x[i];
    __nv_bfloat16 h0, l0, h1, l1, h2, l2, h3, l3;
    split_bf16(a.x, h0, l0); split_bf16(a.y, h1, l1);
    split_bf16(a.z, h2, l2); split_bf16(a.w, h3, l3);
    __nv_bfloat162 hA = __halves2bfloat162(h0, h1), hB = __halves2bfloat162(h2, h3);
    __nv_bfloat162 lA = __halves2bfloat162(l0, l1), lB = __halves2bfloat162(l2, l3);
    hi[i] = make_uint2(*(uint32_t*)&hA, *(uint32_t*)&hB);
    lo[i] = make_uint2(*(uint32_t*)&lA, *(uint32_t*)&lB);
}

__global__ void prep_weight(const float* __restrict__ W, __nv_bfloat16* __restrict__ hi,
                            __nv_bfloat16* __restrict__ lo, int K, int N) {
    int idx = blockIdx.x * 256 + threadIdx.x;
    if (idx >= K * N) return;
    int k = idx / N, n = idx % N;
    __nv_bfloat16 h, l;
    split_bf16(W[idx], h, l);
    hi[(long)n * K + k] = h;
    lo[(long)n * K + k] = l;
}

// =====================================================================
// bf16x3 mma GEMM: relu(A@W + b). CTA 128x128, K=256, 8 warps (4m x 2n).
// mode 0: write fp32 C;  mode 1: write bf16 hi/lo split (Chi/Clo).
// =====================================================================
#define ROWB 144
#define TILE_B (128 * ROWB)
#define GEMM_SMEM (4 * TILE_B)

__global__ void __launch_bounds__(256, 2) mma_gemm(
    const __nv_bfloat16* __restrict__ Ahi, const __nv_bfloat16* __restrict__ Alo,
    const __nv_bfloat16* __restrict__ Bhi, const __nv_bfloat16* __restrict__ Blo,
    const float* __restrict__ bias, float* __restrict__ C,
    __nv_bfloat16* __restrict__ Chi, __nv_bfloat16* __restrict__ Clo,
    int Ncols, int mode)
{
    extern __shared__ char smc[];
    const uint32_t s0  = smem_u32(smc);
    const uint32_t sAh = s0;
    const uint32_t sAl = s0 + TILE_B;
    const uint32_t sBh = s0 + 2 * TILE_B;
    const uint32_t sBl = s0 + 3 * TILE_B;

    const int tid  = threadIdx.x;
    const int wid  = tid >> 5;
    const int lane = tid & 31;
    const int wm   = wid >> 1;
    const int wn   = wid & 1;

    const long mBase = (long)blockIdx.y * 128;
    const int  nBase = blockIdx.x * 128;

    const __nv_bfloat16* Ah = Ahi + mBase * GK;
    const __nv_bfloat16* Al = Alo + mBase * GK;
    const __nv_bfloat16* Bh = Bhi + (long)nBase * GK;
    const __nv_bfloat16* Bl = Blo + (long)nBase * GK;

    float acc[2][8][4];
    #pragma unroll
    for (int a = 0; a < 2; a++)
        #pragma unroll
        for (int b = 0; b < 8; b++)
            #pragma unroll
            for (int c = 0; c < 4; c++) acc[a][b][c] = 0.f;

    const int lrow = tid >> 3;
    const int lq   = tid & 7;
    const uint32_t aOff = (uint32_t)(wm * 32 + (lane & 15)) * ROWB + (lane >> 4) * 16;
    const uint32_t bOff = (uint32_t)(wn * 64 + (lane & 15)) * ROWB + (lane >> 4) * 16;

    for (int kt = 0; kt < 4; kt++) {
        __syncthreads();
        #pragma unroll
        for (int it = 0; it < 4; it++) {
            int r = lrow + it * 32;
            long gsrc = (long)r * GK + kt * 64 + lq * 8;
            uint32_t sdst = (uint32_t)r * ROWB + lq * 16;
            *(uint4*)(smc + 0 * TILE_B + sdst) = *(const uint4*)(Ah + gsrc);
            *(uint4*)(smc + 1 * TILE_B + sdst) = *(const uint4*)(Al + gsrc);
            *(uint4*)(smc + 2 * TILE_B + sdst) = *(const uint4*)(Bh + gsrc);
            *(uint4*)(smc + 3 * TILE_B + sdst) = *(const uint4*)(Bl + gsrc);
        }
        __syncthreads();

        #pragma unroll
        for (int ks = 0; ks < 4; ks++) {
            const uint32_t kByte = ks * 32;
            uint32_t Bf[16], Af[8], Af2[8];
            #pragma unroll
            for (int c = 0; c < 4; c++) {
                uint32_t ad = sBh + bOff + (uint32_t)c * (16 * ROWB) + kByte;
                LDSM4(Bf[c*4+0], Bf[c*4+1], Bf[c*4+2], Bf[c*4+3], ad);
            }
            #pragma unroll
            for (int mt = 0; mt < 2; mt++) {
                uint32_t ad = sAh + aOff + (uint32_t)mt * (16 * ROWB) + kByte;
                LDSM4(Af[mt*4+0], Af[mt*4+1], Af[mt*4+2], Af[mt*4+3], ad);
            }
            #pragma unroll
            for (int mt = 0; mt < 2; mt++) {
                uint32_t ad = sAl + aOff + (uint32_t)mt * (16 * ROWB) + kByte;
                LDSM4(Af2[mt*4+0], Af2[mt*4+1], Af2[mt*4+2], Af2[mt*4+3], ad);
            }
            #pragma unroll
            for (int mt = 0; mt < 2; mt++)
                #pragma unroll
                for (int c = 0; c < 4; c++) {
                    MMA16816(acc[mt][c*2+0], Af[mt*4+0], Af[mt*4+1], Af[mt*4+2], Af[mt*4+3],
                             Bf[c*4+0], Bf[c*4+2]);
                    MMA16816(acc[mt][c*2+1], Af[mt*4+0], Af[mt*4+1], Af[mt*4+2], Af[mt*4+3],
                             Bf[c*4+1], Bf[c*4+3]);
                    MMA16816(acc[mt][c*2+0], Af2[mt*4+0], Af2[mt*4+1], Af2[mt*4+2], Af2[mt*4+3],
                             Bf[c*4+0], Bf[c*4+2]);
                    MMA16816(acc[mt][c*2+1], Af2[mt*4+0], Af2[mt*4+1], Af2[mt*4+2], Af2[mt*4+3],
                             Bf[c*4+1], Bf[c*4+3]);
                }
            #pragma unroll
            for (int c = 0; c < 4; c++) {
                uint32_t ad = sBl + bOff + (uint32_t)c * (16 * ROWB) + kByte;
                LDSM4(Bf[c*4+0], Bf[c*4+1], Bf[c*4+2], Bf[c*4+3], ad);
            }
            #pragma unroll
            for (int mt = 0; mt < 2; mt++)
                #pragma unroll
                for (int c = 0; c < 4; c++) {
                    MMA16816(acc[mt][c*2+0], Af[mt*4+0], Af[mt*4+1], Af[mt*4+2], Af[mt*4+3],
                             Bf[c*4+0], Bf[c*4+2]);
                    MMA16816(acc[mt][c*2+1], Af[mt*4+0], Af[mt*4+1], Af[mt*4+2], Af[mt*4+3],
                             Bf[c*4+1], Bf[c*4+3]);
                }
        }
    }

    const int group = lane >> 2;
    const int tig   = lane & 3;
    #pragma unroll
    for (int mt = 0; mt < 2; mt++) {
        long r0 = mBase + wm * 32 + mt * 16 + group;
        long r1 = r0 + 8;
        #pragma unroll
        for (int nt = 0; nt < 8; nt++) {
            int col = nBase + wn * 64 + (nt >> 1) * 16 + (nt & 1) * 8 + tig * 2;
            float b0 = bias[col], b1 = bias[col + 1];
            float v00 = fmaxf(acc[mt][nt][0] + b0, 0.f);
            float v01 = fmaxf(acc[mt][nt][1] + b1, 0.f);
            float v10 = fmaxf(acc[mt][nt][2] + b0, 0.f);
            float v11 = fmaxf(acc[mt][nt][3] + b1, 0.f);
            if (mode == 0) {
                *(float2*)(C + r0 * Ncols + col) = make_float2(v00, v01);
                *(float2*)(C + r1 * Ncols + col) = make_float2(v10, v11);
            } else {
                __nv_bfloat16 h00, l00, h01, l01, h10, l10, h11, l11;
                split_bf16(v00, h00, l00); split_bf16(v01, h01, l01);
                split_bf16(v10, h10, l10); split_bf16(v11, h11, l11);
                *(__nv_bfloat162*)(Chi + r0 * Ncols + col) = __halves2bfloat162(h00, h01);
                *(__nv_bfloat162*)(Clo + r0 * Ncols + col) = __halves2bfloat162(l00, l01);
                *(__nv_bfloat162*)(Chi + r1 * Ncols + col) = __halves2bfloat162(h10, h11);
                *(__nv_bfloat162*)(Clo + r1 * Ncols + col) = __halves2bfloat162(l10, l11);
            }
        }
    }
}

// =====================================================================
// Fused attention, all-HMMA:
//   phase1: S = q@k^T  (bf16x3, K=512)
//   phase2: masked softmax -> att gmem + P hi/lo smem
//   phase3: ctx = P@v  (bf16x3, hid chunks of 64) -> ctx hi/lo gmem
// smem layout (bytes):
//   [0,65536)           s_sc fp32 scores
//   [65536,139264)      phase1 chunk bufs qh/ql/kh/kl (4 x 18432)
//   [65536,100352)      Phi   (128 x 272)      (phase2/3)
//   [100352,135168)     Plo
//   [135168,152576)     vThi  (64 x 272)       (phase3)
//   [152576,169984)     vTlo
// =====================================================================
#define ROWP 272
#define OFF_PHI 65536
#define OFF_PLO 100352
#define OFF_VTH 135168
#define OFF_VTL 152576
#define ATT_SMEM 169984

__global__ void __launch_bounds__(256, 1) attention_mma(
    const __nv_bfloat16* __restrict__ qhi, const __nv_bfloat16* __restrict__ qlo,
    const __nv_bfloat16* __restrict__ khi, const __nv_bfloat16* __restrict__ klo,
    const __nv_bfloat16* __restrict__ vhi, const __nv_bfloat16* __restrict__ vlo,
    const float* __restrict__ mask, float* __restrict__ att,
    __nv_bfloat16* __restrict__ ctxhi, __nv_bfloat16* __restrict__ ctxlo)
{
    extern __shared__ char sm[];
    float* s_sc = (float*)sm;
    const uint32_t s0 = smem_u32(sm);

    const int b    = blockIdx.x;
    const int tid  = threadIdx.x;
    const int wid  = tid >> 5;
    const int lane = tid & 31;
    const int wm   = wid >> 1;
    const int wn   = wid & 1;
    const int lrow = tid >> 3;
    const int lq   = tid & 7;
    const int group = lane >> 2;
    const int tig   = lane & 3;

    // ---------------- phase 1: S = q @ k^T ----------------
    {
        const __nv_bfloat16* qh = qhi + (long)b * NN * KD;
        const __nv_bfloat16* ql = qlo + (long)b * NN * KD;
        const __nv_bfloat16* kh = khi + (long)b * NN * KD;
        const __nv_bfloat16* kl = klo + (long)b * NN * KD;

        const uint32_t sQh = s0 + 65536;
        const uint32_t sQl = sQh + TILE_B;
        const uint32_t sKh = sQh + 2 * TILE_B;
        const uint32_t sKl = sQh + 3 * TILE_B;

        float acc[2][8][4];
        #pragma unroll
        for (int a = 0; a < 2; a++)
            #pragma unroll
            for (int bb = 0; bb < 8; bb++)
                #pragma unroll
                for (int c = 0; c < 4; c++) acc[a][bb][c] = 0.f;

        const uint32_t aOff = (uint32_t)(wm * 32 + (lane & 15)) * ROWB + (lane >> 4) * 16;
        const uint32_t bOff = (uint32_t)(wn * 64 + (lane & 15)) * ROWB + (lane >> 4) * 16;

        for (int kt = 0; kt < 8; kt++) {
            __syncthreads();
            #pragma unroll
            for (int it = 0; it < 4; it++) {
                int r = lrow + it * 32;
                long gsrc = (long)r * KD + kt * 64 + lq * 8;
                uint32_t sdst = (uint32_t)r * ROWB + lq * 16;
                *(uint4*)(sm + 65536 + 0 * TILE_B + sdst) = *(const uint4*)(qh + gsrc);
                *(uint4*)(sm + 65536 + 1 * TILE_B + sdst) = *(const uint4*)(ql + gsrc);
                *(uint4*)(sm + 65536 + 2 * TILE_B + sdst) = *(const uint4*)(kh + gsrc);
                *(uint4*)(sm + 65536 + 3 * TILE_B + sdst) = *(const uint4*)(kl + gsrc);
            }
            __syncthreads();

            #pragma unroll
            for (int ks = 0; ks < 4; ks++) {
                const uint32_t kByte = ks * 32;
                uint32_t Bf[16], Af[8], Af2[8];
                #pragma unroll
                for (int c = 0; c < 4; c++) {
                    uint32_t ad = sKh + bOff + (uint32_t)c * (16 * ROWB) + kByte;
                    LDSM4(Bf[c*4+0], Bf[c*4+1], Bf[c*4+2], Bf[c*4+3], ad);
                }
                #pragma unroll
                for (int mt = 0; mt < 2; mt++) {
                    uint32_t ad = sQh + aOff + (uint32_t)mt * (16 * ROWB) + kByte;
                    LDSM4(Af[mt*4+0], Af[mt*4+1], Af[mt*4+2], Af[mt*4+3], ad);
                }
                #pragma unroll
                for (int mt = 0; mt < 2; mt++) {
                    uint32_t ad = sQl + aOff + (uint32_t)mt * (16 * ROWB) + kByte;
                    LDSM4(Af2[mt*4+0], Af2[mt*4+1], Af2[mt*4+2], Af2[mt*4+3], ad);
                }
                #pragma unroll
                for (int mt = 0; mt < 2; mt++)
                    #pragma unroll
                    for (int c = 0; c < 4; c++) {
                        MMA16816(acc[mt][c*2+0], Af[mt*4+0], Af[mt*4+1], Af[mt*4+2], Af[mt*4+3],
                                 Bf[c*4+0], Bf[c*4+2]);
                        MMA16816(acc[mt][c*2+1], Af[mt*4+0], Af[mt*4+1], Af[mt*4+2], Af[mt*4+3],
                                 Bf[c*4+1], Bf[c*4+3]);
                        MMA16816(acc[mt][c*2+0], Af2[mt*4+0], Af2[mt*4+1], Af2[mt*4+2], Af2[mt*4+3],
                                 Bf[c*4+0], Bf[c*4+2]);
                        MMA16816(acc[mt][c*2+1], Af2[mt*4+0], Af2[mt*4+1], Af2[mt*4+2], Af2[mt*4+3],
                                 Bf[c*4+1], Bf[c*4+3]);
                    }
                #pragma unroll
                for (int c = 0; c < 4; c++) {
                    uint32_t ad = sKl + bOff + (uint32_t)c * (16 * ROWB) + kByte;
                    LDSM4(Bf[c*4+0], Bf[c*4+1], Bf[c*4+2], Bf[c*4+3], ad);
                }
                #pragma unroll
                for (int mt = 0; mt < 2; mt++)
                    #pragma unroll
                    for (int c = 0; c < 4; c++) {
                        MMA16816(acc[mt][c*2+0], Af[mt*4+0], Af[mt*4+1], Af[mt*4+2], Af[mt*4+3],
                                 Bf[c*4+0], Bf[c*4+2]);
                        MMA16816(acc[mt][c*2+1], Af[mt*4+0], Af[mt*4+1], Af[mt*4+2], Af[mt*4+3],
                                 Bf[c*4+1], Bf[c*4+3]);
                    }
            }
        }
        __syncthreads();
        // scores -> smem fp32
        #pragma unroll
        for (int mt = 0; mt < 2; mt++) {
            int r0 = wm * 32 + mt * 16 + group;
            int r1 = r0 + 8;
            #pragma unroll
            for (int nt = 0; nt < 8; nt++) {
                int col = wn * 64 + (nt >> 1) * 16 + (nt & 1) * 8 + tig * 2;
                *(float2*)(s_sc + r0 * 128 + col) = make_float2(acc[mt][nt][0], acc[mt][nt][1]);
                *(float2*)(s_sc + r1 * 128 + col) = make_float2(acc[mt][nt][2], acc[mt][nt][3]);
            }
        }
    }
    __syncthreads();

    // ---------------- phase 2: masked softmax ----------------
    {
        const float* mb = mask + (long)b * NN * NN;
        float* attb = att + (long)b * NN * NN;
        for (int r = 0; r < 16; r++) {
            int row = wid * 16 + r;
            float vals[4];
            float mx = -1e30f;
            #pragma unroll
            for (int c = 0; c < 4; c++) {
                int col = lane + c * 32;
                float m  = mb[row * 128 + col];
                float sc = s_sc[row * 128 + col];
                float vv = sc * m - 1000.0f * (1.0f - m);
                vals[c] = vv;
                mx = fmaxf(mx, vv);
            }
            #pragma unroll
            for (int off = 16; off; off >>= 1)
                mx = fmaxf(mx, __shfl_xor_sync(0xffffffffu, mx, off));
            float sum = 0.f;
            #pragma unroll
            for (int c = 0; c < 4; c++) {
                vals[c] = __expf(vals[c] - mx);
                sum += vals[c];
            }
            #pragma unroll
            for (int off = 16; off; off >>= 1)
                sum += __shfl_xor_sync(0xffffffffu, sum, off);
            float inv = 1.0f / sum;
            #pragma unroll
            for (int c = 0; c < 4; c++) {
                int col = lane + c * 32;
                float p = vals[c] * inv;
                attb[row * 128 + col] = p;
                __nv_bfloat16 h, l;
                split_bf16(p, h, l);
                *(__nv_bfloat16*)(sm + OFF_PHI + row * ROWP + col * 2) = h;
                *(__nv_bfloat16*)(sm + OFF_PLO + row * ROWP + col * 2) = l;
            }
        }
    }

    // ---------------- phase 3: ctx = P @ v ----------------
    {
        const __nv_bfloat16* vhb = vhi + (long)b * NN * HID;
        const __nv_bfloat16* vlb = vlo + (long)b * NN * HID;
        __nv_bfloat16* chb = ctxhi + (long)b * NN * HID;
        __nv_bfloat16* clb = ctxlo + (long)b * NN * HID;

        const uint32_t sPh = s0 + OFF_PHI;
        const uint32_t sPl = s0 + OFF_PLO;
        const uint32_t sVh = s0 + OFF_VTH;
        const uint32_t sVl = s0 + OFF_VTL;

        const uint32_t aOffP = (uint32_t)(wm * 32 + (lane & 15)) * ROWP + (lane >> 4) * 16;
        const uint32_t bOffV = (uint32_t)(wn * 32 + (lane & 15)) * ROWP + (lane >> 4) * 16;

        for (int hc = 0; hc < 4; hc++) {
            __syncthreads();
            // transpose-load vT chunk: [h(64), node(128)]
            for (int idx = tid; idx < 64 * 128; idx += 256) {
                int node = idx >> 6;
                int h = idx & 63;
                __nv_bfloat16 a = vhb[(long)node * HID + hc * 64 + h];
                __nv_bfloat16 c = vlb[(long)node * HID + hc * 64 + h];
                *(__nv_bfloat16*)(sm + OFF_VTH + h * ROWP + node * 2) = a;
                *(__nv_bfloat16*)(sm + OFF_VTL + h * ROWP + node * 2) = c;
            }
            __syncthreads();

            float acc2[2][4][4];
            #pragma unroll
            for (int a = 0; a < 2; a++)
                #pragma unroll
                for (int bb = 0; bb < 4; bb++)
                    #pragma unroll
                    for (int c = 0; c < 4; c++) acc2[a][bb][c] = 0.f;

            #pragma unroll
            for (int ks = 0; ks < 8; ks++) {
                const uint32_t kByte = ks * 32;
                uint32_t Bf[8], Af[8], Af2[8];
                #pragma unroll
                for (int c = 0; c < 2; c++) {
                    uint32_t ad = sVh + bOffV + (uint32_t)c * (16 * ROWP) + kByte;
                    LDSM4(Bf[c*4+0], Bf[c*4+1], Bf[c*4+2], Bf[c*4+3], ad);
                }
                #pragma unroll
                for (int mt = 0; mt < 2; mt++) {
                    uint32_t ad = sPh + aOffP + (uint32_t)mt * (16 * ROWP) + kByte;
                    LDSM4(Af[mt*4+0], Af[mt*4+1], Af[mt*4+2], Af[mt*4+3], ad);
                }
                #pragma unroll
                for (int mt = 0; mt < 2; mt++) {
                    uint32_t ad = sPl + aOffP + (uint32_t)mt * (16 * ROWP) + kByte;
                    LDSM4(Af2[mt*4+0], Af2[mt*4+1], Af2[mt*4+2], Af2[mt*4+3], ad);
                }
                #pragma unroll
                for (int mt = 0; mt < 2; mt++)
                    #pragma unroll
                    for (int c = 0; c < 2; c++) {
                        MMA16816(acc2[mt][c*2+0], Af[mt*4+0], Af[mt*4+1], Af[mt*4+2], Af[mt*4+3],
                                 Bf[c*4+0], Bf[c*4+2]);
                        MMA16816(acc2[mt][c*2+1], Af[mt*4+0], Af[mt*4+1], Af[mt*4+2], Af[mt*4+3],
                                 Bf[c*4+1], Bf[c*4+3]);
                        MMA16816(acc2[mt][c*2+0], Af2[mt*4+0], Af2[mt*4+1], Af2[mt*4+2], Af2[mt*4+3],
                                 Bf[c*4+0], Bf[c*4+2]);
                        MMA16816(acc2[mt][c*2+1], Af2[mt*4+0], Af2[mt*4+1], Af2[mt*4+2], Af2[mt*4+3],
                                 Bf[c*4+1], Bf[c*4+3]);
                    }
                #pragma unroll
                for (int c = 0; c < 2; c++) {
                    uint32_t ad = sVl + bOffV + (uint32_t)c * (16 * ROWP) + kByte;
                    LDSM4(Bf[c*4+0], Bf[c*4+1], Bf[c*4+2], Bf[c*4+3], ad);
                }
                #pragma unroll
                for (int mt = 0; mt < 2; mt++)
                    #pragma unroll
                    for (int c = 0; c < 2; c++) {
                        MMA16816(acc2[mt][c*2+0], Af[mt*4+0], Af[mt*4+1], Af[mt*4+2], Af[mt*4+3],
                                 Bf[c*4+0], Bf[c*4+2]);
                        MMA16816(acc2[mt][c*2+1], Af[mt*4+0], Af[mt*4+1], Af[mt*4+2], Af[mt*4+3],
                                 Bf[c*4+1], Bf[c*4+3]);
                    }
            }

            #pragma unroll
            for (int mt = 0; mt < 2; mt++) {
                int r0 = wm * 32 + mt * 16 + group;
                int r1 = r0 + 8;
                #pragma unroll
                for (int nt = 0; nt < 4; nt++) {
                    int col = hc * 64 + wn * 32 + (nt >> 1) * 16 + (nt & 1) * 8 + tig * 2;
                    __nv_bfloat16 h00, l00, h01, l01, h10, l10, h11, l11;
                    split_bf16(acc2[mt][nt][0], h00, l00);
                    split_bf16(acc2[mt][nt][1], h01, l01);
                    split_bf16(acc2[mt][nt][2], h10, l10);
                    split_bf16(acc2[mt][nt][3], h11, l11);
                    *(__nv_bfloat162*)(chb + (long)r0 * HID + col) = __halves2bfloat162(h00, h01);
                    *(__nv_bfloat162*)(clb + (long)r0 * HID + col) = __halves2bfloat162(l00, l01);
                    *(__nv_bfloat162*)(chb + (long)r1 * HID + col) = __halves2bfloat162(h10, h11);
                    *(__nv_bfloat162*)(clb + (long)r1 * HID + col) = __halves2bfloat162(l10, l11);
                }
            }
        }
    }
}

// =====================================================================
extern "C" void kernel_launch(void* const* d_in, const int* in_sizes, int n_in,
                              void* d_out, int out_size)
{
    const float* x    = (const float*)d_in[0];
    const float* mask = (const float*)d_in[1];
    const float* Wv   = (const float*)d_in[2];
    const float* bv   = (const float*)d_in[3];
    const float* Wq   = (const float*)d_in[4];
    const float* bq   = (const float*)d_in[5];
    const float* Wk   = (const float*)d_in[6];
    const float* bk   = (const float*)d_in[7];
    const float* Wo   = (const float*)d_in[8];
    const float* bo   = (const float*)d_in[9];

    float* out = (float*)d_out;

    float* pattd;
    cudaGetSymbolAddress((void**)&pattd, g_att_dummy);

    __nv_bfloat16 *xhi, *xlo, *qhi, *qlo, *khi, *klo, *vhi, *vlo, *chi, *clo;
    cudaGetSymbolAddress((void**)&xhi, g_xhi);
    cudaGetSymbolAddress((void**)&xlo, g_xlo);
    cudaGetSymbolAddress((void**)&qhi, g_qhi);
    cudaGetSymbolAddress((void**)&qlo, g_qlo);
    cudaGetSymbolAddress((void**)&khi, g_khi);
    cudaGetSymbolAddress((void**)&klo, g_klo);
    cudaGetSymbolAddress((void**)&vhi, g_vhi);
    cudaGetSymbolAddress((void**)&vlo, g_vlo);
    cudaGetSymbolAddress((void**)&chi, g_chi);
    cudaGetSymbolAddress((void**)&clo, g_clo);

    __nv_bfloat16 *wvhi, *wvlo, *wqhi, *wqlo, *wkhi, *wklo, *wohi, *wolo;
    cudaGetSymbolAddress((void**)&wvhi, g_wvhi);
    cudaGetSymbolAddress((void**)&wvlo, g_wvlo);
    cudaGetSymbolAddress((void**)&wqhi, g_wqhi);
    cudaGetSymbolAddress((void**)&wqlo, g_wqlo);
    cudaGetSymbolAddress((void**)&wkhi, g_wkhi);
    cudaGetSymbolAddress((void**)&wklo, g_wklo);
    cudaGetSymbolAddress((void**)&wohi, g_wohi);
    cudaGetSymbolAddress((void**)&wolo, g_wolo);

    float* patt = ((long)out_size >= TOT_ELEMS) ? (out + OUT_ELEMS) : pattd;

    cudaFuncSetAttribute(attention_mma,
                         cudaFuncAttributeMaxDynamicSharedMemorySize, ATT_SMEM);
    cudaFuncSetAttribute(mma_gemm,
                         cudaFuncAttributeMaxDynamicSharedMemorySize, GEMM_SMEM);

    {
        long n4 = (long)MROWS * GK / 4;
        split_x_kernel<<<(unsigned)((n4 + 255) / 256), 256>>>(
            (const float4*)x, (uint2*)xhi, (uint2*)xlo, n4);
    }
    prep_weight<<<(GK*HID  + 255)/256, 256>>>(Wv, wvhi, wvlo, GK, HID);
    prep_weight<<<(GK*KD   + 255)/256, 256>>>(Wq, wqhi, wqlo, GK, KD);
    prep_weight<<<(GK*KD   + 255)/256, 256>>>(Wk, wkhi, wklo, GK, KD);
    prep_weight<<<(HID*DOUT+ 255)/256, 256>>>(Wo, wohi, wolo, HID, DOUT);

    const int mTiles = MROWS / 128;
    // v,q,k GEMMs -> bf16 hi/lo split outputs
    mma_gemm<<<dim3(HID/128, mTiles), 256, GEMM_SMEM>>>(
        xhi, xlo, wvhi, wvlo, bv, nullptr, vhi, vlo, HID, 1);
    mma_gemm<<<dim3(KD/128,  mTiles), 256, GEMM_SMEM>>>(
        xhi, xlo, wqhi, wqlo, bq, nullptr, qhi, qlo, KD, 1);
    mma_gemm<<<dim3(KD/128,  mTiles), 256, GEMM_SMEM>>>(
        xhi, xlo, wkhi, wklo, bk, nullptr, khi, klo, KD, 1);

    attention_mma<<<BATCH, 256, ATT_SMEM>>>(qhi, qlo, khi, klo, vhi, vlo,
                                            mask, patt, chi, clo);

    // out GEMM -> fp32
    mma_gemm<<<dim3(DOUT/128, mTiles), 256, GEMM_SMEM>>>(
        chi, clo, wohi, wolo, bo, out, nullptr, nullptr, DOUT, 0);
}